// round 1
// baseline (speedup 1.0000x reference)
#include <cuda_runtime.h>

// Problem constants (fixed shapes per reference)
#define B_   2
#define N_   262144
#define C_   64
#define T_   192                 // tile points per CTA
#define R_   199                 // smem row stride (T+6 rows used, +1 pad, odd for bank spread)
#define NROW (T_ + 6)            // 198 gathered rows incl. halo 3 each side
#define NTILE ((N_ + T_ - 1) / T_)  // 1366
#define EPS_ 1e-5f

// Scratch + folded params (statically allocated: no cudaMalloc anywhere)
__device__ float g_tmp[(size_t)B_ * N_ * C_];           // 128 MB intermediate between blocks
__device__ float g_wfold[2][3][192][64];                // [blk][layer][i*3+k][o] : BN-folded, transposed
__device__ float g_bfold[2][3][64];                     // [blk][layer][o]
__device__ int   g_idx64;                               // 1 if index arrays are int64

// ---------------------------------------------------------------------------
// Prep: fold BN into conv weights, transpose to [i*3+k][o]; detect idx dtype.
// ---------------------------------------------------------------------------
__global__ void prep_kernel(const float* __restrict__ conv_w,
                            const float* __restrict__ bg,
                            const float* __restrict__ bb,
                            const float* __restrict__ bm,
                            const float* __restrict__ bv,
                            const void*  __restrict__ pa1)
{
    int idx = blockIdx.x * blockDim.x + threadIdx.x;

    if (idx == 0) {
        // int64 perm values < 2^31 -> high words all zero. An int32 permutation
        // cannot have 4 zeros among its first 8 entries (values are distinct).
        const int* p = (const int*)pa1;
        g_idx64 = (p[1] == 0 && p[3] == 0 && p[5] == 0 && p[7] == 0) ? 1 : 0;
    }

    if (idx < 2 * 3 * 64) {                  // bias fold: [blk][L][c]
        int o = idx & 63;
        int L = (idx >> 6) % 3;
        int bk = idx / 192;
        float sc = bg[idx] * rsqrtf(bv[idx] + EPS_);
        g_bfold[bk][L][o] = bb[idx] - bm[idx] * sc;
    }

    if (idx < 2 * 3 * 64 * 64 * 3) {         // conv_w: [blk][L][o][i][k]
        int k = idx % 3;
        int i = (idx / 3) & 63;
        int o = (idx / 192) & 63;
        int L = (idx / 12288) % 3;
        int bk = idx / 36864;
        int bni = (bk * 3 + L) * 64 + o;
        float sc = bg[bni] * rsqrtf(bv[bni] + EPS_);
        g_wfold[bk][L][i * 3 + k][o] = conv_w[idx] * sc;
    }
}

// ---------------------------------------------------------------------------
// Fused block kernel: gather + 3x(conv-bn[-relu]) + residual relu + scatter
// One CTA = one T_-point tile of one batch. Channel-major smem buffers.
// ---------------------------------------------------------------------------
__global__ void __launch_bounds__(256, 1)
mc_block_kernel(const float* __restrict__ xin,
                const void*  __restrict__ pav,
                float* __restrict__ out,
                int bk)
{
    extern __shared__ float smf[];
    float* buf0   = smf;                     // [64][R_] gathered x (residual source)
    float* buf1   = smf + 64 * R_;           // h1
    float* buf2   = smf + 2 * 64 * R_;       // h2
    float* w_s    = smf + 3 * 64 * R_;       // [192][64] folded weights, current layer
    float* bias_s = w_s + 192 * 64;          // [64]

    const int b    = blockIdx.y;
    const int ts   = blockIdx.x * T_;
    const int tid  = threadIdx.x;
    const int lane = tid & 31;
    const int co   = (tid >> 5) * 8;         // 8 warps x 8 output channels

    const bool is64 = (g_idx64 != 0);
    const int*       pa32 = (const int*)pav;
    const long long* pa64 = (const long long*)pav;

    // ---- gather tile (+halo) into buf0, channel-major; zero outside [0,N) ----
    {
        const int c4 = (tid & 15) * 4;
        for (int r = tid >> 4; r < NROW; r += 16) {
            int gp = ts - 3 + r;
            float4 v = make_float4(0.f, 0.f, 0.f, 0.f);
            if (gp >= 0 && gp < N_) {
                long long row = is64 ? pa64[(size_t)b * N_ + gp]
                                     : (long long)pa32[(size_t)b * N_ + gp];
                v = *(const float4*)(xin + ((size_t)b * N_ + (size_t)row) * C_ + c4);
            }
            buf0[(c4 + 0) * R_ + r] = v.x;
            buf0[(c4 + 1) * R_ + r] = v.y;
            buf0[(c4 + 2) * R_ + r] = v.z;
            buf0[(c4 + 3) * R_ + r] = v.w;
        }
    }

    #pragma unroll
    for (int L = 0; L < 3; ++L) {
        __syncthreads();   // prev-layer stores done before weight overwrite
        {
            const float4* wsrc = (const float4*)&g_wfold[bk][L][0][0];
            float4* wdst = (float4*)w_s;
            for (int i = tid; i < (192 * 64) / 4; i += 256) wdst[i] = wsrc[i];
            if (tid < 64) bias_s[tid] = g_bfold[bk][L][tid];
        }
        __syncthreads();

        const float* in   = (L == 0) ? buf0 : (L == 1) ? buf1 : buf2;
        float*       outb = (L == 0) ? buf1 : buf2;

        const int pb = L + 1;            // first output point (buffer coords)
        const int pe = T_ + 5 - L;       // one past last
        const int NS = (L == 2) ? 6 : 7; // point slots per lane

        int  pc[7];
        bool pvld[7];
        #pragma unroll
        for (int j = 0; j < 7; ++j) {
            int p = pb + lane + 32 * j;
            pvld[j] = (j < NS) && (p < pe);
            pc[j] = pvld[j] ? p : pb;    // clamp so loads stay in-bounds
        }

        float bl[8];
        #pragma unroll
        for (int o = 0; o < 8; ++o) bl[o] = bias_s[co + o];

        float acc[7][8];
        #pragma unroll
        for (int j = 0; j < 7; ++j)
            #pragma unroll
            for (int o = 0; o < 8; ++o) acc[j][o] = bl[o];

        for (int ci = 0; ci < 64; ++ci) {
            const float* wr = w_s + ci * 192 + co;
            float w0[8], w1[8], w2[8];
            *(float4*)&w0[0] = *(const float4*)(wr);
            *(float4*)&w0[4] = *(const float4*)(wr + 4);
            *(float4*)&w1[0] = *(const float4*)(wr + 64);
            *(float4*)&w1[4] = *(const float4*)(wr + 68);
            *(float4*)&w2[0] = *(const float4*)(wr + 128);
            *(float4*)&w2[4] = *(const float4*)(wr + 132);

            const float* inr = in + ci * R_;
            #pragma unroll
            for (int j = 0; j < 7; ++j) {
                if (j >= NS) break;      // compile-time after unroll of L
                float xm = inr[pc[j] - 1];
                float x0 = inr[pc[j]];
                float xp = inr[pc[j] + 1];
                #pragma unroll
                for (int o = 0; o < 8; ++o) {
                    acc[j][o] = fmaf(w0[o], xm, acc[j][o]);
                    acc[j][o] = fmaf(w1[o], x0, acc[j][o]);
                    acc[j][o] = fmaf(w2[o], xp, acc[j][o]);
                }
            }
        }

        if (L < 2) {
            // ReLU; force zero outside the real sequence so padding semantics hold
            #pragma unroll
            for (int j = 0; j < 7; ++j) {
                if (!pvld[j]) continue;
                int gp = ts - 3 + pc[j];
                bool inside = (gp >= 0) && (gp < N_);
                #pragma unroll
                for (int o = 0; o < 8; ++o) {
                    float vv = inside ? fmaxf(acc[j][o], 0.f) : 0.f;
                    outb[(co + o) * R_ + pc[j]] = vv;
                }
            }
        } else {
            // residual + ReLU + scatter: out[b][pa[gp]][:] = relu(x + h3)
            #pragma unroll
            for (int j = 0; j < 6; ++j) {
                int p = pc[j];
                int gp = ts - 3 + p;          // in [ts, ts + T_)
                if (gp >= N_) continue;       // last partial tile
                long long row = is64 ? pa64[(size_t)b * N_ + gp]
                                     : (long long)pa32[(size_t)b * N_ + gp];
                float r8[8];
                #pragma unroll
                for (int o = 0; o < 8; ++o)
                    r8[o] = fmaxf(buf0[(co + o) * R_ + p] + acc[j][o], 0.f);
                float* op = out + ((size_t)b * N_ + (size_t)row) * C_ + co;
                *(float4*)(op)     = *(float4*)&r8[0];
                *(float4*)(op + 4) = *(float4*)&r8[4];
            }
        }
    }
}

// ---------------------------------------------------------------------------
extern "C" void kernel_launch(void* const* d_in, const int* in_sizes, int n_in,
                              void* d_out, int out_size)
{
    const float* x      = (const float*)d_in[0];
    const void*  pa1    = d_in[1];
    // d_in[2] = idx_re_1 (unused: re∘pa = id, scatter uses pa)
    const void*  pa2    = d_in[3];
    // d_in[4] = idx_re_2 (unused)
    const float* conv_w = (const float*)d_in[5];
    const float* bg     = (const float*)d_in[6];
    const float* bb     = (const float*)d_in[7];
    const float* bm     = (const float*)d_in[8];
    const float* bv     = (const float*)d_in[9];
    float* out = (float*)d_out;

    size_t smem = (size_t)(3 * 64 * R_ + 192 * 64 + 64) * sizeof(float); // 202,240 B
    cudaFuncSetAttribute(mc_block_kernel,
                         cudaFuncAttributeMaxDynamicSharedMemorySize, (int)smem);

    void* tmpp = nullptr;
    cudaGetSymbolAddress(&tmpp, g_tmp);

    prep_kernel<<<(73728 + 255) / 256, 256>>>(conv_w, bg, bb, bm, bv, pa1);

    dim3 grid(NTILE, B_);
    mc_block_kernel<<<grid, 256, smem>>>(x, pa1, (float*)tmpp, 0);
    mc_block_kernel<<<grid, 256, smem>>>((const float*)tmpp, pa2, out, 1);
}

// round 3
// speedup vs baseline: 2.6648x; 2.6648x over previous
#include <cuda_runtime.h>
#include <cuda_bf16.h>
#include <cstdint>

// ---------------- problem constants ----------------
#define B_    2
#define N_    262144
#define T_    122                     // valid output points per CTA
#define NTILE ((N_ + T_ - 1) / T_)    // 2149
#define EPS_  1e-5f

// ---------------- smem layout (bytes) ----------------
// 6 activation buffers (X,H1,H2 x {hi,lo}) of 128 rows x 144B (64 bf16 + pad)
// 2 weight-fragment buffers (double-buffered cp.async), 48KB each
// bias: 3 x 64 floats
#define ROWSTRIDE 144
#define BUFBYTES  (128 * ROWSTRIDE)        // 18432
#define SM_BUF    0
#define WBYTES    49152                    // 3 taps x 2 parts x 8 nb x 4 kb x 32 lanes x 8B
#define SM_W      (6 * BUFBYTES)           // 110592
#define SM_BIAS   (SM_W + 2 * WBYTES)      // 208896
#define SM_TOTAL  (SM_BIAS + 1024)         // 209920

// ---------------- device globals (no allocs allowed) ----------------
__device__ float   g_tmp[(size_t)B_ * N_ * 64];     // inter-block scratch (128 MB)
__device__ __align__(16) uint32_t g_wfrag[73728];   // [bk][L][t][part][nb][kb][lane][reg]
__device__ float   g_bias[2][192];                  // folded bias [blk][L*64+o]
__device__ int     g_idx64;

// ---------------- helpers ----------------
__device__ __forceinline__ uint32_t smem_u32(const void* p) {
    uint32_t a;
    asm("{ .reg .u64 t; cvta.to.shared.u64 t, %1; cvt.u32.u64 %0, t; }" : "=r"(a) : "l"(p));
    return a;
}
__device__ __forceinline__ uint16_t f2bf(float f) {
    __nv_bfloat16 h = __float2bfloat16_rn(f);
    return *(uint16_t*)&h;
}
__device__ __forceinline__ float bf2f(uint32_t u) {  // low 16 bits = bf16 pattern
    return __uint_as_float((u & 0xFFFFu) << 16);
}

__device__ __forceinline__ void mma_bf16(float d[4], const uint32_t a[4],
                                         uint32_t b0, uint32_t b1) {
    asm volatile(
        "mma.sync.aligned.m16n8k16.row.col.f32.bf16.bf16.f32 "
        "{%0,%1,%2,%3}, {%4,%5,%6,%7}, {%8,%9}, {%0,%1,%2,%3};"
        : "+f"(d[0]), "+f"(d[1]), "+f"(d[2]), "+f"(d[3])
        : "r"(a[0]), "r"(a[1]), "r"(a[2]), "r"(a[3]), "r"(b0), "r"(b1));
}

#define LDSM4(a, addr)                                                         \
    asm volatile("ldmatrix.sync.aligned.m8n8.x4.shared.b16 {%0,%1,%2,%3}, [%4];" \
        : "=r"((a)[0]), "=r"((a)[1]), "=r"((a)[2]), "=r"((a)[3]) : "r"(addr))

#define CPA16(dst, src)                                                        \
    asm volatile("cp.async.cg.shared.global [%0], [%1], 16;"                   \
        :: "r"(dst), "l"(src) : "memory")
#define CPA_COMMIT() asm volatile("cp.async.commit_group;" ::: "memory")

// ---------------------------------------------------------------------------
// Prep: fold BN into conv weights, split bf16 hi/lo, emit mma.sync B-fragments
// in final lane/register layout; fold bias; detect index dtype.
// ---------------------------------------------------------------------------
__global__ void prep_kernel(const float* __restrict__ conv_w,
                            const float* __restrict__ bg,
                            const float* __restrict__ bb,
                            const float* __restrict__ bm,
                            const float* __restrict__ bv,
                            const void*  __restrict__ pa1)
{
    int idx = blockIdx.x * blockDim.x + threadIdx.x;

    if (idx == 0) {
        const int* p = (const int*)pa1;   // int64 perm -> zero high words
        g_idx64 = (p[1] == 0 && p[3] == 0 && p[5] == 0 && p[7] == 0) ? 1 : 0;
    }
    if (idx < 384) {                      // bias fold [bk][L][o]
        int o = idx & 63, L = (idx >> 6) % 3, bk = idx / 192;
        float sc = bg[idx] * rsqrtf(bv[idx] + EPS_);
        g_bias[bk][L * 64 + o] = bb[idx] - bm[idx] * sc;
    }
    if (idx < 73728) {
        int q = idx;
        int reg  = q & 1;  q >>= 1;
        int lane = q & 31; q >>= 5;
        int kb   = q & 3;  q >>= 2;
        int nb   = q & 7;  q >>= 3;
        int part = q & 1;  q >>= 1;
        int t    = q % 3;  q /= 3;
        int L    = q % 3;
        int bk   = q / 3;

        int n  = nb * 8 + (lane >> 2);                 // output channel
        int k0 = kb * 16 + reg * 8 + (lane & 3) * 2;   // input channel pair
        int bni = (bk * 3 + L) * 64 + n;
        float sc = bg[bni] * rsqrtf(bv[bni] + EPS_);

        uint16_t hv[2];
        #pragma unroll
        for (int h = 0; h < 2; ++h) {
            int i = k0 + h;
            float w = conv_w[(((size_t)(bk * 3 + L) * 64 + n) * 64 + i) * 3 + t] * sc;
            uint16_t hi = f2bf(w);
            hv[h] = (part == 0) ? hi : f2bf(w - bf2f(hi));
        }
        g_wfrag[idx] = (uint32_t)hv[0] | ((uint32_t)hv[1] << 16);
    }
}

// ---------------------------------------------------------------------------
// Fused block: gather -> 3 x (mma.sync conv + BN + act) -> residual -> scatter
// One CTA = 122 output points (128-row buffer), 256 threads, 8 warps x M=16.
// ---------------------------------------------------------------------------
__global__ void __launch_bounds__(256, 1)
mc_block_kernel(const float* __restrict__ xin,
                const void*  __restrict__ pav,
                float* __restrict__ out,
                int bk)
{
    extern __shared__ uint8_t smem[];
    const uint32_t sbase = smem_u32(smem);
    const int tid = threadIdx.x, wid = tid >> 5, lane = tid & 31;
    const int b = blockIdx.y;
    const int ts = blockIdx.x * T_;
    const bool is64 = (g_idx64 != 0);
    const int*       pa32 = (const int*)pav;
    const long long* pa64 = (const long long*)pav;

    if (tid < 192) ((float*)(smem + SM_BIAS))[tid] = g_bias[bk][tid];

    // ---- prefetch layer-0 weight fragments (48KB) via cp.async ----
    {
        const uint8_t* src = (const uint8_t*)g_wfrag + (size_t)(bk * 3) * WBYTES;
        #pragma unroll
        for (int i = 0; i < 12; ++i) {
            int e = tid + i * 256;
            CPA16(sbase + SM_W + e * 16, src + (size_t)e * 16);
        }
        CPA_COMMIT();
    }

    // ---- gather 128 rows (points ts-3 .. ts+124), bf16 hi/lo split ----
    {
        const int r = tid >> 1, h = tid & 1;          // 2 threads per row
        int gp = ts - 3 + r;
        bool ok = (gp >= 0) && (gp < N_);
        const float4* src = nullptr;
        if (ok) {
            long long prow = is64 ? pa64[(size_t)b * N_ + gp]
                                  : (long long)pa32[(size_t)b * N_ + gp];
            src = (const float4*)(xin + ((size_t)b * N_ + (size_t)prow) * 64 + h * 32);
        }
        uint8_t* bh0 = smem + SM_BUF;
        uint8_t* bl0 = bh0 + BUFBYTES;
        #pragma unroll
        for (int i = 0; i < 8; ++i) {
            float4 v = ok ? src[i] : make_float4(0.f, 0.f, 0.f, 0.f);
            uint16_t h0 = f2bf(v.x), h1 = f2bf(v.y), h2 = f2bf(v.z), h3 = f2bf(v.w);
            uint16_t l0 = f2bf(v.x - bf2f(h0)), l1 = f2bf(v.y - bf2f(h1));
            uint16_t l2 = f2bf(v.z - bf2f(h2)), l3 = f2bf(v.w - bf2f(h3));
            uint32_t off = (uint32_t)(r * ROWSTRIDE + h * 64 + i * 8);
            *(uint2*)(bh0 + off) = make_uint2((uint32_t)h0 | ((uint32_t)h1 << 16),
                                              (uint32_t)h2 | ((uint32_t)h3 << 16));
            *(uint2*)(bl0 + off) = make_uint2((uint32_t)l0 | ((uint32_t)l1 << 16),
                                              (uint32_t)l2 | ((uint32_t)l3 << 16));
        }
    }

    const int pr = wid * 16;                          // warp's 16-row slab

    // A-operand ldmatrix row offsets per tap (clamped; edges are zeroed later)
    uint32_t aoff[3];
    #pragma unroll
    for (int t = 0; t < 3; ++t) {
        int rr = pr + t - 1 + (lane & 15);
        rr = rr < 0 ? 0 : (rr > 127 ? 127 : rr);
        aoff[t] = (uint32_t)(rr * ROWSTRIDE) + ((lane >> 4) * 16);
    }

    #pragma unroll
    for (int L = 0; L < 3; ++L) {
        // prefetch next layer's weights into the other buffer
        if (L < 2) {
            const uint8_t* src = (const uint8_t*)g_wfrag + (size_t)(bk * 3 + L + 1) * WBYTES;
            uint32_t dst = sbase + SM_W + (uint32_t)(((L + 1) & 1) * WBYTES);
            #pragma unroll
            for (int i = 0; i < 12; ++i) {
                int e = tid + i * 256;
                CPA16(dst + e * 16, src + (size_t)e * 16);
            }
            CPA_COMMIT();
            asm volatile("cp.async.wait_group 1;" ::: "memory");
        } else {
            asm volatile("cp.async.wait_group 0;" ::: "memory");
        }
        __syncthreads();   // weights ready + prev-layer activation stores visible

        const uint8_t* wp = smem + SM_W + (size_t)((L & 1) * WBYTES);
        const uint32_t bufA_hi = sbase + SM_BUF + (uint32_t)(2 * L) * BUFBYTES;
        const uint32_t bufA_lo = bufA_hi + BUFBYTES;

        float d[8][4];
        #pragma unroll
        for (int nb = 0; nb < 8; ++nb)
            #pragma unroll
            for (int j = 0; j < 4; ++j) d[nb][j] = 0.f;

        #pragma unroll
        for (int t = 0; t < 3; ++t) {
            #pragma unroll
            for (int kb = 0; kb < 4; ++kb) {
                uint32_t a[4];
                LDSM4(a, bufA_hi + aoff[t] + kb * 32);

                uint2 bhi[8];
                #pragma unroll
                for (int nb = 0; nb < 8; ++nb) {       // A_hi * B_hi
                    bhi[nb] = *(const uint2*)(wp + (size_t)((((t * 2 + 0) * 8 + nb) * 4 + kb) * 256 + lane * 8));
                    mma_bf16(d[nb], a, bhi[nb].x, bhi[nb].y);
                }
                #pragma unroll
                for (int nb = 0; nb < 8; ++nb) {       // A_hi * B_lo
                    uint2 blo = *(const uint2*)(wp + (size_t)((((t * 2 + 1) * 8 + nb) * 4 + kb) * 256 + lane * 8));
                    mma_bf16(d[nb], a, blo.x, blo.y);
                }
                LDSM4(a, bufA_lo + aoff[t] + kb * 32);
                #pragma unroll
                for (int nb = 0; nb < 8; ++nb)         // A_lo * B_hi
                    mma_bf16(d[nb], a, bhi[nb].x, bhi[nb].y);
            }
        }

        // ---- epilogue ----
        const float* bias = (const float*)(smem + SM_BIAS) + L * 64;
        const int g0 = pr + (lane >> 2);

        if (L < 2) {
            uint8_t* oh = smem + SM_BUF + (uint32_t)(2 * (L + 1)) * BUFBYTES;
            uint8_t* ol = oh + BUFBYTES;
            #pragma unroll
            for (int rh = 0; rh < 2; ++rh) {
                const int r = g0 + rh * 8;
                const int gp = ts - 3 + r;
                const bool valid = (r >= L + 1) && (r <= 126 - L) && (gp >= 0) && (gp < N_);
                #pragma unroll
                for (int nb = 0; nb < 8; ++nb) {
                    const int c0 = nb * 8 + (lane & 3) * 2;
                    float v0 = valid ? fmaxf(d[nb][rh * 2 + 0] + bias[c0], 0.f) : 0.f;
                    float v1 = valid ? fmaxf(d[nb][rh * 2 + 1] + bias[c0 + 1], 0.f) : 0.f;
                    uint16_t h0 = f2bf(v0), h1 = f2bf(v1);
                    uint16_t l0 = f2bf(v0 - bf2f(h0)), l1 = f2bf(v1 - bf2f(h1));
                    uint32_t off = (uint32_t)(r * ROWSTRIDE + c0 * 2);
                    *(uint32_t*)(oh + off) = (uint32_t)h0 | ((uint32_t)h1 << 16);
                    *(uint32_t*)(ol + off) = (uint32_t)l0 | ((uint32_t)l1 << 16);
                }
            }
        } else {
            const uint8_t* rhb = smem + SM_BUF;        // original x hi
            const uint8_t* rlb = rhb + BUFBYTES;       // original x lo
            #pragma unroll
            for (int rh = 0; rh < 2; ++rh) {
                const int r = g0 + rh * 8;
                const int gp = ts - 3 + r;
                if (r >= 3 && r <= 124 && gp < N_) {
                    long long prow = is64 ? pa64[(size_t)b * N_ + gp]
                                          : (long long)pa32[(size_t)b * N_ + gp];
                    float* op = out + ((size_t)b * N_ + (size_t)prow) * 64;
                    #pragma unroll
                    for (int nb = 0; nb < 8; ++nb) {
                        const int c0 = nb * 8 + (lane & 3) * 2;
                        uint32_t off = (uint32_t)(r * ROWSTRIDE + c0 * 2);
                        uint32_t xh = *(const uint32_t*)(rhb + off);
                        uint32_t xl = *(const uint32_t*)(rlb + off);
                        float2 o2;
                        o2.x = fmaxf(bf2f(xh) + bf2f(xl)
                                     + d[nb][rh * 2 + 0] + bias[c0], 0.f);
                        o2.y = fmaxf(bf2f(xh >> 16) + bf2f(xl >> 16)
                                     + d[nb][rh * 2 + 1] + bias[c0 + 1], 0.f);
                        *(float2*)(op + c0) = o2;
                    }
                }
            }
        }
        __syncthreads();   // epilogue stores done before next layer / prefetch reuse
    }
}

// ---------------------------------------------------------------------------
extern "C" void kernel_launch(void* const* d_in, const int* in_sizes, int n_in,
                              void* d_out, int out_size)
{
    const float* x      = (const float*)d_in[0];
    const void*  pa1    = d_in[1];
    // d_in[2] = idx_re_1 (unused: re ∘ pa = id, scatter uses pa)
    const void*  pa2    = d_in[3];
    // d_in[4] = idx_re_2 (unused)
    const float* conv_w = (const float*)d_in[5];
    const float* bg     = (const float*)d_in[6];
    const float* bb     = (const float*)d_in[7];
    const float* bm     = (const float*)d_in[8];
    const float* bv     = (const float*)d_in[9];
    float* out = (float*)d_out;

    cudaFuncSetAttribute(mc_block_kernel,
                         cudaFuncAttributeMaxDynamicSharedMemorySize, SM_TOTAL);

    void* tmpp = nullptr;
    cudaGetSymbolAddress(&tmpp, g_tmp);

    prep_kernel<<<(73728 + 255) / 256, 256>>>(conv_w, bg, bb, bm, bv, pa1);

    dim3 grid(NTILE, B_);
    mc_block_kernel<<<grid, 256, SM_TOTAL>>>(x, pa1, (float*)tmpp, 0);
    mc_block_kernel<<<grid, 256, SM_TOTAL>>>((const float*)tmpp, pa2, out, 1);
}

// round 4
// speedup vs baseline: 3.1054x; 1.1653x over previous
#include <cuda_runtime.h>
#include <cuda_bf16.h>
#include <cstdint>

// ---------------- problem constants ----------------
#define B_    2
#define N_    262144
#define T_    250                     // valid output points per CTA
#define ROWS_ 256                     // buffer rows (halo 3 each side)
#define NTILE ((N_ + T_ - 1) / T_)    // 1049
#define EPS_  1e-5f

// ---------------- smem layout (bytes) ----------------
// 4 activation buffers (ping-pong pairs x {hi,lo}) of 256 rows x 144B
// 1 weight-fragment buffer 48KB (re-staged per layer)
// bias: 3 x 64 floats
#define ROWSTRIDE 144
#define BUFBYTES  (ROWS_ * ROWSTRIDE)      // 36864
#define SM_BUF    0
#define WBYTES    49152                    // 3 taps x 2 parts x 8 nb x 4 kb x 32 lanes x 8B
#define SM_W      (4 * BUFBYTES)           // 147456
#define SM_BIAS   (SM_W + WBYTES)          // 196608
#define SM_TOTAL  (SM_BIAS + 1024)         // 197632

// ---------------- device globals (no allocs allowed) ----------------
__device__ float   g_tmp[(size_t)B_ * N_ * 64];     // inter-block scratch (128 MB)
__device__ __align__(16) uint32_t g_wfrag[73728];   // [bk][L][t][part][nb][kb][lane][reg]
__device__ float   g_bias[2][192];                  // folded bias [blk][L*64+o]
__device__ int     g_idx64;

// ---------------- helpers ----------------
__device__ __forceinline__ uint32_t smem_u32(const void* p) {
    uint32_t a;
    asm("{ .reg .u64 t; cvta.to.shared.u64 t, %1; cvt.u32.u64 %0, t; }" : "=r"(a) : "l"(p));
    return a;
}
__device__ __forceinline__ uint16_t f2bf(float f) {
    __nv_bfloat16 h = __float2bfloat16_rn(f);
    return *(uint16_t*)&h;
}
__device__ __forceinline__ float bf2f(uint32_t u) {  // low 16 bits = bf16 pattern
    return __uint_as_float((u & 0xFFFFu) << 16);
}
// pack (v0,v1) -> {hi bf16x2, lo bf16x2} with v0 in the low half
__device__ __forceinline__ uint2 pack2(float v0, float v1) {
    uint32_t h;
    asm("cvt.rn.bf16x2.f32 %0, %1, %2;" : "=r"(h) : "f"(v1), "f"(v0));
    float l0 = v0 - __uint_as_float(h << 16);
    float l1 = v1 - __uint_as_float(h & 0xFFFF0000u);
    uint32_t l;
    asm("cvt.rn.bf16x2.f32 %0, %1, %2;" : "=r"(l) : "f"(l1), "f"(l0));
    return make_uint2(h, l);
}

__device__ __forceinline__ void mma_bf16(float d[4], const uint32_t a[4],
                                         uint32_t b0, uint32_t b1) {
    asm volatile(
        "mma.sync.aligned.m16n8k16.row.col.f32.bf16.bf16.f32 "
        "{%0,%1,%2,%3}, {%4,%5,%6,%7}, {%8,%9}, {%0,%1,%2,%3};"
        : "+f"(d[0]), "+f"(d[1]), "+f"(d[2]), "+f"(d[3])
        : "r"(a[0]), "r"(a[1]), "r"(a[2]), "r"(a[3]), "r"(b0), "r"(b1));
}

#define LDSM4(a, addr)                                                         \
    asm volatile("ldmatrix.sync.aligned.m8n8.x4.shared.b16 {%0,%1,%2,%3}, [%4];" \
        : "=r"((a)[0]), "=r"((a)[1]), "=r"((a)[2]), "=r"((a)[3]) : "r"(addr))

#define CPA16(dst, src)                                                        \
    asm volatile("cp.async.cg.shared.global [%0], [%1], 16;"                   \
        :: "r"(dst), "l"(src) : "memory")
#define CPA_COMMIT() asm volatile("cp.async.commit_group;" ::: "memory")
#define CPA_WAIT0()  asm volatile("cp.async.wait_group 0;" ::: "memory")

// ---------------------------------------------------------------------------
// Prep: fold BN into conv weights, split bf16 hi/lo, emit mma.sync B-fragments
// in final lane/register layout; fold bias; detect index dtype.
// ---------------------------------------------------------------------------
__global__ void prep_kernel(const float* __restrict__ conv_w,
                            const float* __restrict__ bg,
                            const float* __restrict__ bb,
                            const float* __restrict__ bm,
                            const float* __restrict__ bv,
                            const void*  __restrict__ pa1)
{
    int idx = blockIdx.x * blockDim.x + threadIdx.x;

    if (idx == 0) {
        const int* p = (const int*)pa1;   // int64 perm -> zero high words
        g_idx64 = (p[1] == 0 && p[3] == 0 && p[5] == 0 && p[7] == 0) ? 1 : 0;
    }
    if (idx < 384) {                      // bias fold [bk][L][o]
        int o = idx & 63, L = (idx >> 6) % 3, bk = idx / 192;
        float sc = bg[idx] * rsqrtf(bv[idx] + EPS_);
        g_bias[bk][L * 64 + o] = bb[idx] - bm[idx] * sc;
    }
    if (idx < 73728) {
        int q = idx;
        int reg  = q & 1;  q >>= 1;
        int lane = q & 31; q >>= 5;
        int kb   = q & 3;  q >>= 2;
        int nb   = q & 7;  q >>= 3;
        int part = q & 1;  q >>= 1;
        int t    = q % 3;  q /= 3;
        int L    = q % 3;
        int bk   = q / 3;

        int n  = nb * 8 + (lane >> 2);                 // output channel
        int k0 = kb * 16 + reg * 8 + (lane & 3) * 2;   // input channel pair
        int bni = (bk * 3 + L) * 64 + n;
        float sc = bg[bni] * rsqrtf(bv[bni] + EPS_);

        uint16_t hv[2];
        #pragma unroll
        for (int h = 0; h < 2; ++h) {
            int i = k0 + h;
            float w = conv_w[(((size_t)(bk * 3 + L) * 64 + n) * 64 + i) * 3 + t] * sc;
            uint16_t hi = f2bf(w);
            hv[h] = (part == 0) ? hi : f2bf(w - bf2f(hi));
        }
        g_wfrag[idx] = (uint32_t)hv[0] | ((uint32_t)hv[1] << 16);
    }
}

// ---------------------------------------------------------------------------
// Fused block: gather -> 3 x (mma.sync conv + BN + act) -> residual -> scatter
// One CTA = 250 output points (256-row buffer), 256 threads, 8 warps x M=32.
// Residual x is re-gathered from gmem at the final epilogue (frees smem).
// ---------------------------------------------------------------------------
__global__ void __launch_bounds__(256, 1)
mc_block_kernel(const float* __restrict__ xin,
                const void*  __restrict__ pav,
                float* __restrict__ out,
                int bk)
{
    extern __shared__ uint8_t smem[];
    const uint32_t sbase = smem_u32(smem);
    const int tid = threadIdx.x, wid = tid >> 5, lane = tid & 31;
    const int b = blockIdx.y;
    const int ts = blockIdx.x * T_;
    const bool is64 = (g_idx64 != 0);
    const int*       pa32 = (const int*)pav;
    const long long* pa64 = (const long long*)pav;

    if (tid < 192) ((float*)(smem + SM_BIAS))[tid] = g_bias[bk][tid];

    // ---- stage layer-0 weight fragments (48KB) via cp.async ----
    {
        const uint8_t* src = (const uint8_t*)g_wfrag + (size_t)(bk * 3) * WBYTES;
        #pragma unroll
        for (int i = 0; i < 12; ++i) {
            int e = tid + i * 256;
            CPA16(sbase + SM_W + e * 16, src + (size_t)e * 16);
        }
        CPA_COMMIT();
    }

    // ---- gather 256 rows (points ts-3 .. ts+252) into pair0, bf16 hi/lo ----
    {
        const int r = tid;                 // one thread per row
        int gp = ts - 3 + r;
        bool ok = (gp >= 0) && (gp < N_);
        const float4* src = nullptr;
        if (ok) {
            long long prow = is64 ? pa64[(size_t)b * N_ + gp]
                                  : (long long)pa32[(size_t)b * N_ + gp];
            src = (const float4*)(xin + ((size_t)b * N_ + (size_t)prow) * 64);
        }
        uint8_t* bh0 = smem + SM_BUF;              // pair0 hi
        uint8_t* bl0 = bh0 + BUFBYTES;             // pair0 lo
        #pragma unroll
        for (int i = 0; i < 16; ++i) {
            float4 v = ok ? src[i] : make_float4(0.f, 0.f, 0.f, 0.f);
            uint2 p01 = pack2(v.x, v.y);
            uint2 p23 = pack2(v.z, v.w);
            uint32_t off = (uint32_t)(r * ROWSTRIDE + i * 8);
            *(uint2*)(bh0 + off) = make_uint2(p01.x, p23.x);
            *(uint2*)(bl0 + off) = make_uint2(p01.y, p23.y);
        }
    }

    CPA_WAIT0();
    __syncthreads();

    // A-operand ldmatrix row offsets: [slab][tap], rows clamped to [0,255]
    uint32_t aoff[2][3];
    #pragma unroll
    for (int s2 = 0; s2 < 2; ++s2)
        #pragma unroll
        for (int t = 0; t < 3; ++t) {
            int rr = wid * 32 + s2 * 16 + t - 1 + (lane & 15);
            rr = rr < 0 ? 0 : (rr > 255 ? 255 : rr);
            aoff[s2][t] = (uint32_t)(rr * ROWSTRIDE) + ((lane >> 4) * 16);
        }

    const uint8_t* wl = smem + SM_W + lane * 8;

    #pragma unroll
    for (int L = 0; L < 3; ++L) {
        const int inp = (L == 1) ? 1 : 0;          // L0:p0, L1:p1, L2:p0
        const uint32_t inHi = sbase + SM_BUF + (uint32_t)(inp * 2) * BUFBYTES;
        const uint32_t inLo = inHi + BUFBYTES;

        float d[2][8][4];
        #pragma unroll
        for (int s2 = 0; s2 < 2; ++s2)
            #pragma unroll
            for (int nb = 0; nb < 8; ++nb)
                #pragma unroll
                for (int j = 0; j < 4; ++j) d[s2][nb][j] = 0.f;

        #pragma unroll
        for (int t = 0; t < 3; ++t) {
            #pragma unroll
            for (int kb = 0; kb < 4; ++kb) {
                uint32_t a0[4], a1[4];
                LDSM4(a0, inHi + aoff[0][t] + kb * 32);
                LDSM4(a1, inHi + aoff[1][t] + kb * 32);

                uint2 bh[8];
                #pragma unroll
                for (int nb = 0; nb < 8; ++nb) {       // A_hi * B_hi
                    bh[nb] = *(const uint2*)(wl + (size_t)((((t * 2 + 0) * 8 + nb) * 4 + kb) * 256));
                    mma_bf16(d[0][nb], a0, bh[nb].x, bh[nb].y);
                    mma_bf16(d[1][nb], a1, bh[nb].x, bh[nb].y);
                }
                #pragma unroll
                for (int nb = 0; nb < 8; ++nb) {       // A_hi * B_lo
                    uint2 bl = *(const uint2*)(wl + (size_t)((((t * 2 + 1) * 8 + nb) * 4 + kb) * 256));
                    mma_bf16(d[0][nb], a0, bl.x, bl.y);
                    mma_bf16(d[1][nb], a1, bl.x, bl.y);
                }
                LDSM4(a0, inLo + aoff[0][t] + kb * 32);
                LDSM4(a1, inLo + aoff[1][t] + kb * 32);
                #pragma unroll
                for (int nb = 0; nb < 8; ++nb) {       // A_lo * B_hi
                    mma_bf16(d[0][nb], a0, bh[nb].x, bh[nb].y);
                    mma_bf16(d[1][nb], a1, bh[nb].x, bh[nb].y);
                }
            }
        }

        // ---- epilogue ----
        const float* bias = (const float*)(smem + SM_BIAS) + L * 64;

        if (L < 2) {
            const int outp = (L == 0) ? 1 : 0;
            uint8_t* oh = smem + SM_BUF + (uint32_t)(outp * 2) * BUFBYTES;
            uint8_t* ol = oh + BUFBYTES;
            #pragma unroll
            for (int s2 = 0; s2 < 2; ++s2) {
                #pragma unroll
                for (int rh = 0; rh < 2; ++rh) {
                    const int r = wid * 32 + s2 * 16 + rh * 8 + (lane >> 2);
                    const int gp = ts - 3 + r;
                    const bool valid = (r >= L + 1) && (r <= 254 - L) && (gp >= 0) && (gp < N_);
                    #pragma unroll
                    for (int nb = 0; nb < 8; ++nb) {
                        const int c0 = nb * 8 + (lane & 3) * 2;
                        float v0 = valid ? fmaxf(d[s2][nb][rh * 2 + 0] + bias[c0], 0.f) : 0.f;
                        float v1 = valid ? fmaxf(d[s2][nb][rh * 2 + 1] + bias[c0 + 1], 0.f) : 0.f;
                        uint2 p = pack2(v0, v1);
                        uint32_t off = (uint32_t)(r * ROWSTRIDE + c0 * 2);
                        *(uint32_t*)(oh + off) = p.x;
                        *(uint32_t*)(ol + off) = p.y;
                    }
                }
            }
            __syncthreads();     // epi visible + W buffer free
            {                    // stage next layer's weights
                const uint8_t* src = (const uint8_t*)g_wfrag + (size_t)(bk * 3 + L + 1) * WBYTES;
                #pragma unroll
                for (int i = 0; i < 12; ++i) {
                    int e = tid + i * 256;
                    CPA16(sbase + SM_W + e * 16, src + (size_t)e * 16);
                }
                CPA_COMMIT();
                CPA_WAIT0();
            }
            __syncthreads();
        } else {
            // residual (re-gathered from gmem) + ReLU + permuted scatter
            #pragma unroll
            for (int s2 = 0; s2 < 2; ++s2) {
                #pragma unroll
                for (int rh = 0; rh < 2; ++rh) {
                    const int r = wid * 32 + s2 * 16 + rh * 8 + (lane >> 2);
                    const int gp = ts - 3 + r;
                    if (r >= 3 && r <= 252 && gp < N_) {
                        long long prow = is64 ? pa64[(size_t)b * N_ + gp]
                                              : (long long)pa32[(size_t)b * N_ + gp];
                        const float* xp = xin + ((size_t)b * N_ + (size_t)prow) * 64;
                        float* op = out + ((size_t)b * N_ + (size_t)prow) * 64;
                        #pragma unroll
                        for (int nb = 0; nb < 8; ++nb) {
                            const int c0 = nb * 8 + (lane & 3) * 2;
                            float2 xv = *(const float2*)(xp + c0);
                            float2 o2;
                            o2.x = fmaxf(xv.x + d[s2][nb][rh * 2 + 0] + bias[c0], 0.f);
                            o2.y = fmaxf(xv.y + d[s2][nb][rh * 2 + 1] + bias[c0 + 1], 0.f);
                            *(float2*)(op + c0) = o2;
                        }
                    }
                }
            }
        }
    }
}

// ---------------------------------------------------------------------------
extern "C" void kernel_launch(void* const* d_in, const int* in_sizes, int n_in,
                              void* d_out, int out_size)
{
    const float* x      = (const float*)d_in[0];
    const void*  pa1    = d_in[1];
    // d_in[2] = idx_re_1 (unused: re ∘ pa = id, scatter uses pa)
    const void*  pa2    = d_in[3];
    // d_in[4] = idx_re_2 (unused)
    const float* conv_w = (const float*)d_in[5];
    const float* bg     = (const float*)d_in[6];
    const float* bb     = (const float*)d_in[7];
    const float* bm     = (const float*)d_in[8];
    const float* bv     = (const float*)d_in[9];
    float* out = (float*)d_out;

    cudaFuncSetAttribute(mc_block_kernel,
                         cudaFuncAttributeMaxDynamicSharedMemorySize, SM_TOTAL);

    void* tmpp = nullptr;
    cudaGetSymbolAddress(&tmpp, g_tmp);

    prep_kernel<<<(73728 + 255) / 256, 256>>>(conv_w, bg, bb, bm, bv, pa1);

    dim3 grid(NTILE, B_);
    mc_block_kernel<<<grid, 256, SM_TOTAL>>>(x, pa1, (float*)tmpp, 0);
    mc_block_kernel<<<grid, 256, SM_TOTAL>>>((const float*)tmpp, pa2, out, 1);
}